// round 7
// baseline (speedup 1.0000x reference)
#include <cuda_runtime.h>
#include <cstdint>

#define N_NODES  10000
#define N_EDGES  320000
#define N_GRAPHS 16
#define D_IN     256
#define D_H      64

// ---------------- device scratch (no allocations allowed) ----------------
__device__ float  g_S[N_NODES * D_H];        // self projection (+bias)
__device__ float  g_X[N_NODES * D_H];        // neighbor projection
__device__ float  g_h1[N_NODES * D_H];       // layer1 output
__device__ float  g_h2[N_NODES * D_H];       // layer2 output
__device__ int    g_rowcnt[N_NODES];         // in-degree histogram (self-zeroing)
__device__ int    g_rowptr[N_NODES + 1];     // CSR row pointers (by dst)
__device__ int    g_cursor[N_NODES];         // placement cursors
__device__ int    g_csr[N_EDGES];            // CSR column indices (src)
__device__ float2 g_Wsp1[D_IN * 128];        // layer1 [Wself|Wneigh] split (hi,lo)
__device__ float2 g_Wsp2[D_H * 128];         // layer2 split
__device__ float2 g_Wsp3[D_H * 128];         // layer3 split

// ---------------- small helpers ----------------

__device__ __forceinline__ uint32_t f2tf32(float f) {
    uint32_t r;
    asm("cvt.rna.tf32.f32 %0, %1;" : "=r"(r) : "f"(f));
    return r;
}

__device__ __forceinline__ void mma_tf32(float* c, const uint32_t* a,
                                         uint32_t b0, uint32_t b1) {
    asm volatile(
        "mma.sync.aligned.m16n8k8.row.col.f32.tf32.tf32.f32 "
        "{%0,%1,%2,%3}, {%4,%5,%6,%7}, {%8,%9}, {%0,%1,%2,%3};"
        : "+f"(c[0]), "+f"(c[1]), "+f"(c[2]), "+f"(c[3])
        : "r"(a[0]), "r"(a[1]), "r"(a[2]), "r"(a[3]), "r"(b0), "r"(b1));
}

__device__ __forceinline__ int warp_incl_scan(int v) {
    int lane = threadIdx.x & 31;
#pragma unroll
    for (int o = 1; o < 32; o <<= 1) {
        int n = __shfl_up_sync(0xffffffffu, v, o);
        if (lane >= o) v += n;
    }
    return v;
}

// ---------------- W split precompute (tf32x3 hi/lo tables) ----------------
__global__ void splitW_kernel(const float* __restrict__ Ws1, const float* __restrict__ Wn1,
                              const float* __restrict__ Ws2, const float* __restrict__ Wn2,
                              const float* __restrict__ Ws3, const float* __restrict__ Wn3) {
    int t = blockIdx.x * blockDim.x + threadIdx.x;
    const float* Ws; const float* Wn; float2* dstp; int idx; int kdim;
    if (t < D_IN * 128) {
        Ws = Ws1; Wn = Wn1; dstp = g_Wsp1; idx = t; kdim = D_IN;
    } else if (t < D_IN * 128 + D_H * 128) {
        Ws = Ws2; Wn = Wn2; dstp = g_Wsp2; idx = t - D_IN * 128; kdim = D_H;
    } else if (t < D_IN * 128 + 2 * D_H * 128) {
        Ws = Ws3; Wn = Wn3; dstp = g_Wsp3; idx = t - D_IN * 128 - D_H * 128; kdim = D_H;
    } else return;
    (void)kdim;
    int k = idx >> 7;
    int n = idx & 127;
    float w = (n < D_H) ? Ws[k * D_H + n] : Wn[k * D_H + (n - D_H)];
    uint32_t hb = f2tf32(w);
    float hf = __uint_as_float(hb);
    uint32_t lb = f2tf32(w - hf);
    dstp[idx] = make_float2(__uint_as_float(hb), __uint_as_float(lb));
}

// ---------------- CSR build ----------------

__global__ void hist_kernel(const int* __restrict__ dst) {
    int t = blockIdx.x * blockDim.x + threadIdx.x;
    if (t * 4 >= N_EDGES) return;
    int4 d4 = *reinterpret_cast<const int4*>(dst + t * 4);
    atomicAdd(&g_rowcnt[d4.x], 1);
    atomicAdd(&g_rowcnt[d4.y], 1);
    atomicAdd(&g_rowcnt[d4.z], 1);
    atomicAdd(&g_rowcnt[d4.w], 1);
}

// single-block prefix sum over 10000 counts -> rowptr, cursor; re-zeroes rowcnt
__global__ void scan_kernel() {
    __shared__ int wsum[32];
    __shared__ int s_total;
    int tid  = threadIdx.x;
    int lane = tid & 31;
    int wid  = tid >> 5;
    int running = 0;

    for (int chunk = 0; chunk < (N_NODES + 1023) / 1024; chunk++) {
        int i = chunk * 1024 + tid;
        int v = 0;
        if (i < N_NODES) {
            v = g_rowcnt[i];
            g_rowcnt[i] = 0;            // self-zero for next launch
        }
        int incl = warp_incl_scan(v);
        if (lane == 31) wsum[wid] = incl;
        __syncthreads();
        if (wid == 0) {
            int wv = wsum[lane];
            int wincl = warp_incl_scan(wv);
            wsum[lane] = wincl;
            if (lane == 31) s_total = wincl;
        }
        __syncthreads();
        int base = (wid > 0) ? wsum[wid - 1] : 0;
        incl += base;
        if (i < N_NODES) {
            g_rowptr[i + 1] = running + incl;
            g_cursor[i]     = running + incl - v;
        }
        if (tid == 0 && chunk == 0) g_rowptr[0] = 0;
        running += s_total;
        __syncthreads();
    }
}

__global__ void place_kernel(const int* __restrict__ src,
                             const int* __restrict__ dst) {
    int t = blockIdx.x * blockDim.x + threadIdx.x;
    if (t * 4 >= N_EDGES) return;
    int4 s4 = *reinterpret_cast<const int4*>(src + t * 4);
    int4 d4 = *reinterpret_cast<const int4*>(dst + t * 4);
    g_csr[atomicAdd(&g_cursor[d4.x], 1)] = s4.x;
    g_csr[atomicAdd(&g_cursor[d4.y], 1)] = s4.y;
    g_csr[atomicAdd(&g_cursor[d4.z], 1)] = s4.z;
    g_csr[atomicAdd(&g_cursor[d4.w], 1)] = s4.w;
}

// ---------------- projection via tensor cores (tf32x3) ----------------
// C[10000 x 128] = A[10000 x K] @ [Wself | Wneigh]; cols 0..63 -> g_S (+bias),
// cols 64..127 -> g_X. One warp owns 16 rows (10000 = 625 x 16), 16 n-tiles,
// mma.m16n8k8 with big/small operand split for fp32-grade accuracy.
template <int K>
__global__ void __launch_bounds__(128)
project_mma(const float* __restrict__ A,
            const float2* __restrict__ Wsp,
            const float* __restrict__ b) {
    const int lane = threadIdx.x & 31;
    const int gid  = lane >> 2;          // 0..7
    const int tig  = lane & 3;           // 0..3
    const int warp = blockIdx.x * 4 + (threadIdx.x >> 5);
    const int r0   = warp * 16;
    if (r0 >= N_NODES) return;

    float c[16][4];
#pragma unroll
    for (int nt = 0; nt < 16; nt++) {
        c[nt][0] = 0.f; c[nt][1] = 0.f; c[nt][2] = 0.f; c[nt][3] = 0.f;
    }

    const float* ArA = A + (size_t)(r0 + gid) * K;
    const float* ArB = A + (size_t)(r0 + gid + 8) * K;

#pragma unroll 2
    for (int kt = 0; kt < K / 8; kt++) {
        const int k0 = kt * 8;
        float af[4];
        af[0] = __ldg(ArA + k0 + tig);
        af[1] = __ldg(ArB + k0 + tig);
        af[2] = __ldg(ArA + k0 + tig + 4);
        af[3] = __ldg(ArB + k0 + tig + 4);
        uint32_t ab[4], as[4];
#pragma unroll
        for (int i = 0; i < 4; i++) {
            ab[i] = f2tf32(af[i]);
            as[i] = f2tf32(af[i] - __uint_as_float(ab[i]));
        }
        const float2* Wr0 = Wsp + (k0 + tig) * 128 + gid;
        const float2* Wr1 = Wsp + (k0 + tig + 4) * 128 + gid;
#pragma unroll
        for (int nt = 0; nt < 16; nt++) {
            float2 w0 = __ldg(Wr0 + nt * 8);
            float2 w1 = __ldg(Wr1 + nt * 8);
            uint32_t b0h = __float_as_uint(w0.x);
            uint32_t b0l = __float_as_uint(w0.y);
            uint32_t b1h = __float_as_uint(w1.x);
            uint32_t b1l = __float_as_uint(w1.y);
            mma_tf32(c[nt], ab, b0h, b1h);   // big*big
            mma_tf32(c[nt], ab, b0l, b1l);   // big*small
            mma_tf32(c[nt], as, b0h, b1h);   // small*big
        }
    }

    const int rA = r0 + gid;
    const int rB = r0 + gid + 8;
#pragma unroll
    for (int nt = 0; nt < 16; nt++) {
        int col = nt * 8 + tig * 2;          // 0..126 within 128
        if (nt < 8) {
            float2 bb = *reinterpret_cast<const float2*>(b + col);
            float2 lo = make_float2(c[nt][0] + bb.x, c[nt][1] + bb.y);
            float2 hi = make_float2(c[nt][2] + bb.x, c[nt][3] + bb.y);
            *reinterpret_cast<float2*>(g_S + rA * D_H + col) = lo;
            *reinterpret_cast<float2*>(g_S + rB * D_H + col) = hi;
        } else {
            int xc = col - 64;
            *reinterpret_cast<float2*>(g_X + rA * D_H + xc) = make_float2(c[nt][0], c[nt][1]);
            *reinterpret_cast<float2*>(g_X + rB * D_H + xc) = make_float2(c[nt][2], c[nt][3]);
        }
    }
}

// ---------------- gather + finalize: out = act(S + mean_{j in N(i)} X_j) ----
template <bool RELU>
__global__ void gather_kernel(float* __restrict__ out) {
    int t    = blockIdx.x * blockDim.x + threadIdx.x;
    int node = t >> 4;
    int lane = t & 15;

    int beg = g_rowptr[node];
    int end = g_rowptr[node + 1];

    float4 acc = make_float4(0.f, 0.f, 0.f, 0.f);
    int p = beg;
    for (; p + 1 < end; p += 2) {
        int s0 = g_csr[p];
        int s1 = g_csr[p + 1];
        float4 v0 = *reinterpret_cast<const float4*>(g_X + s0 * D_H + lane * 4);
        float4 v1 = *reinterpret_cast<const float4*>(g_X + s1 * D_H + lane * 4);
        acc.x += v0.x; acc.y += v0.y; acc.z += v0.z; acc.w += v0.w;
        acc.x += v1.x; acc.y += v1.y; acc.z += v1.z; acc.w += v1.w;
    }
    if (p < end) {
        int s0 = g_csr[p];
        float4 v0 = *reinterpret_cast<const float4*>(g_X + s0 * D_H + lane * 4);
        acc.x += v0.x; acc.y += v0.y; acc.z += v0.z; acc.w += v0.w;
    }

    float inv = 1.f / fmaxf((float)(end - beg), 1.f);
    float4 s4 = *reinterpret_cast<const float4*>(g_S + node * D_H + lane * 4);
    float4 o;
    o.x = s4.x + acc.x * inv;
    o.y = s4.y + acc.y * inv;
    o.z = s4.z + acc.z * inv;
    o.w = s4.w + acc.w * inv;
    if (RELU) {
        o.x = fmaxf(o.x, 0.f); o.y = fmaxf(o.y, 0.f);
        o.z = fmaxf(o.z, 0.f); o.w = fmaxf(o.w, 0.f);
    }
    *reinterpret_cast<float4*>(out + node * D_H + lane * 4) = o;
}

// ---------------- readout + head (graph_id sorted -> contiguous segments) ---
__device__ __forceinline__ int lower_bound_gid(const int* gid, int key) {
    int lo = 0, hi = N_NODES;
    while (lo < hi) {
        int mid = (lo + hi) >> 1;
        if (gid[mid] < key) lo = mid + 1; else hi = mid;
    }
    return lo;
}

__global__ void readout_head_kernel(const float* __restrict__ h,
                                    const int* __restrict__ gid,
                                    const float* __restrict__ Wcls,
                                    const float* __restrict__ bcls,
                                    float* __restrict__ out,
                                    float* __restrict__ out_feat) {
    __shared__ int s_beg, s_end;
    __shared__ float red[4][D_H];
    int g = blockIdx.x;
    if (threadIdx.x == 0) {
        s_beg = lower_bound_gid(gid, g);
        s_end = lower_bound_gid(gid, g + 1);
    }
    __syncthreads();
    int beg = s_beg, end = s_end;
    int c = threadIdx.x & 63;
    int r = threadIdx.x >> 6;   // 0..3

    float acc = 0.f;
    for (int i = beg + r; i < end; i += 4)
        acc += h[i * D_H + c];
    red[r][c] = acc;
    __syncthreads();
    if (r == 0) {
        float m = (red[0][c] + red[1][c] + red[2][c] + red[3][c]) /
                  fmaxf((float)(end - beg), 1.f);
        out_feat[g * D_H + c] = m;
        red[0][c] = m;
    }
    __syncthreads();
    if (threadIdx.x < 2) {
        int j = threadIdx.x;
        float s = bcls[j];
#pragma unroll
        for (int k = 0; k < D_H; k++)
            s = fmaf(red[0][k], Wcls[k * 2 + j], s);
        out[g * 2 + j] = s;
    }
}

// ---------------- launch ----------------

template <typename T>
static T* sym_addr(const void* sym) {
    void* p = nullptr;
    cudaGetSymbolAddress(&p, sym);
    return (T*)p;
}

extern "C" void kernel_launch(void* const* d_in, const int* in_sizes, int n_in,
                              void* d_out, int out_size) {
    const float* feat     = (const float*)d_in[0];
    const int*   src      = (const int*)d_in[1];
    const int*   dst      = (const int*)d_in[2];
    const int*   gid      = (const int*)d_in[3];
    const float* W_self1  = (const float*)d_in[4];
    const float* W_neigh1 = (const float*)d_in[5];
    const float* b1       = (const float*)d_in[6];
    const float* W_self2  = (const float*)d_in[7];
    const float* W_neigh2 = (const float*)d_in[8];
    const float* b2       = (const float*)d_in[9];
    const float* W_self3  = (const float*)d_in[10];
    const float* W_neigh3 = (const float*)d_in[11];
    const float* b3       = (const float*)d_in[12];
    const float* W_cls    = (const float*)d_in[13];
    const float* b_cls    = (const float*)d_in[14];

    float* out      = (float*)d_out;                  // [16, 2]
    float* out_feat = out + N_GRAPHS * 2;             // [16, 64]
    float* h3       = out_feat + N_GRAPHS * D_H;      // [10000, 64]

    float* p_h1 = sym_addr<float>(g_h1);
    float* p_h2 = sym_addr<float>(g_h2);
    float2* p_Wsp1 = sym_addr<float2>(g_Wsp1);
    float2* p_Wsp2 = sym_addr<float2>(g_Wsp2);
    float2* p_Wsp3 = sym_addr<float2>(g_Wsp3);

    const int splitTot = D_IN * 128 + 2 * D_H * 128;  // 49152
    const int projGrid = (N_NODES / 16 + 3) / 4;      // 157 blocks x 4 warps
    const int edgeGrid = (N_EDGES / 4 + 255) / 256;   // 313
    const int gatherGrid = N_NODES * 16 / 256;        // 625

    // ---- weight splits + CSR build ----
    splitW_kernel<<<(splitTot + 255) / 256, 256>>>(W_self1, W_neigh1,
                                                   W_self2, W_neigh2,
                                                   W_self3, W_neigh3);
    hist_kernel<<<edgeGrid, 256>>>(dst);
    scan_kernel<<<1, 1024>>>();
    place_kernel<<<edgeGrid, 256>>>(src, dst);

    // ---- layer 1 (K=256), relu ----
    project_mma<D_IN><<<projGrid, 128>>>(feat, p_Wsp1, b1);
    gather_kernel<true><<<gatherGrid, 256>>>(p_h1);

    // ---- layer 2 (K=64), relu ----
    project_mma<D_H><<<projGrid, 128>>>(p_h1, p_Wsp2, b2);
    gather_kernel<true><<<gatherGrid, 256>>>(p_h2);

    // ---- layer 3 (K=64), no relu -> h3 straight into d_out ----
    project_mma<D_H><<<projGrid, 128>>>(p_h2, p_Wsp3, b3);
    gather_kernel<false><<<gatherGrid, 256>>>(h3);

    // ---- readout + head ----
    readout_head_kernel<<<N_GRAPHS, 256>>>(h3, gid, W_cls, b_cls, out, out_feat);
}

// round 8
// speedup vs baseline: 1.9456x; 1.9456x over previous
#include <cuda_runtime.h>
#include <cstdint>

#define N_NODES  10000
#define N_EDGES  320000
#define N_GRAPHS 16
#define D_IN     256
#define D_H      64

// ---------------- device scratch (no allocations allowed) ----------------
__device__ float g_S[N_NODES * D_H];       // self projection (+bias)
__device__ float g_X[N_NODES * D_H];       // neighbor projection
__device__ float g_h1[N_NODES * D_H];      // layer1 output
__device__ float g_h2[N_NODES * D_H];      // layer2 output
__device__ int   g_rowcnt[N_NODES];        // in-degree histogram (self-zeroing)
__device__ int   g_rowptr[N_NODES + 1];    // CSR row pointers (by dst)
__device__ int   g_cursor[N_NODES];        // placement cursors
__device__ int   g_csr[N_EDGES];           // CSR column indices (src)
__device__ float g_gsum[N_GRAPHS * D_H];   // per-graph readout sums

// ---------------- small helpers ----------------

__device__ __forceinline__ unsigned long long pack2(float lo, float hi) {
    unsigned long long r;
    asm("mov.b64 %0, {%1, %2};" : "=l"(r) : "f"(lo), "f"(hi));
    return r;
}
__device__ __forceinline__ float2 unpack2(unsigned long long v) {
    float2 r;
    asm("mov.b64 {%0, %1}, %2;" : "=f"(r.x), "=f"(r.y) : "l"(v));
    return r;
}
__device__ __forceinline__ void ffma2(unsigned long long& d,
                                      unsigned long long a,
                                      unsigned long long b) {
    asm("fma.rn.f32x2 %0, %1, %2, %0;" : "+l"(d) : "l"(a), "l"(b));
}
__device__ __forceinline__ void cp_async16(uint32_t saddr, const void* gaddr) {
    asm volatile("cp.async.ca.shared.global [%0], [%1], 16;"
                 :: "r"(saddr), "l"(gaddr));
}
__device__ __forceinline__ void cp_commit() {
    asm volatile("cp.async.commit_group;");
}
template <int N>
__device__ __forceinline__ void cp_wait() {
    asm volatile("cp.async.wait_group %0;" :: "n"(N));
}

__device__ __forceinline__ int warp_incl_scan(int v) {
    int lane = threadIdx.x & 31;
#pragma unroll
    for (int o = 1; o < 32; o <<= 1) {
        int n = __shfl_up_sync(0xffffffffu, v, o);
        if (lane >= o) v += n;
    }
    return v;
}

// ================== K1: fused layer-1 projection + dst histogram ==========
// Blocks [0, PROJ_B): warp-autonomous register GEMM (8 rows/warp, K=256).
// Blocks [PROJ_B, PROJ_B+HIST_B): dst histogram (REDG, no return value).
#define PROJ_B 313
#define HIST_B 625

__global__ void __launch_bounds__(128, 3)
fused_proj1_hist(const float* __restrict__ A,
                 const float* __restrict__ Wself,
                 const float* __restrict__ Wneigh,
                 const float* __restrict__ b,
                 const int* __restrict__ dst) {
    if (blockIdx.x >= PROJ_B) {
        // ---- histogram part ----
        int t = (blockIdx.x - PROJ_B) * 128 + threadIdx.x;
        int4 d4 = *reinterpret_cast<const int4*>(dst + t * 4);
        atomicAdd(&g_rowcnt[d4.x], 1);
        atomicAdd(&g_rowcnt[d4.y], 1);
        atomicAdd(&g_rowcnt[d4.z], 1);
        atomicAdd(&g_rowcnt[d4.w], 1);
        return;
    }

    // ---- projection part (K = D_IN = 256) ----
    constexpr int K = D_IN;
    const int lane = threadIdx.x & 31;
    const int warp = blockIdx.x * 4 + (threadIdx.x >> 5);
    const int row0 = warp * 8;
    if (row0 >= N_NODES) return;

    const unsigned long long* Ws = reinterpret_cast<const unsigned long long*>(Wself);
    const unsigned long long* Wn = reinterpret_cast<const unsigned long long*>(Wneigh);
    const float* Arow = A + (size_t)row0 * K;

    unsigned long long s2[8], x2[8];
#pragma unroll
    for (int r = 0; r < 8; r++) { s2[r] = 0ull; x2[r] = 0ull; }

    float4 aA[8], aB[8];
    unsigned long long wsA[4], wnA[4], wsB[4], wnB[4];

    auto loadA = [&](float4* buf, int g) {
#pragma unroll
        for (int r = 0; r < 8; r++)
            buf[r] = __ldcs(reinterpret_cast<const float4*>(Arow + r * K + g * 4));
    };
    auto loadW = [&](unsigned long long* ws, unsigned long long* wn, int g) {
#pragma unroll
        for (int j = 0; j < 4; j++) {
            ws[j] = __ldg(&Ws[(g * 4 + j) * 32 + lane]);
            wn[j] = __ldg(&Wn[(g * 4 + j) * 32 + lane]);
        }
    };
    auto compute = [&](const float4* a,
                       const unsigned long long* ws,
                       const unsigned long long* wn) {
#pragma unroll
        for (int kk = 0; kk < 4; kk++) {
#pragma unroll
            for (int r = 0; r < 8; r++) {
                float av = (kk == 0) ? a[r].x : (kk == 1) ? a[r].y
                         : (kk == 2) ? a[r].z : a[r].w;
                unsigned long long a2 = pack2(av, av);
                ffma2(s2[r], a2, ws[kk]);
                ffma2(x2[r], a2, wn[kk]);
            }
        }
    };

    constexpr int NG = K / 4;
    loadA(aA, 0);
    loadW(wsA, wnA, 0);
#pragma unroll 1
    for (int g2 = 0; g2 < NG / 2; g2++) {
        loadA(aB, 2 * g2 + 1);
        loadW(wsB, wnB, 2 * g2 + 1);
        compute(aA, wsA, wnA);
        int gn = (2 * g2 + 2 < NG) ? 2 * g2 + 2 : NG - 1;   // clamped overfetch
        loadA(aA, gn);
        loadW(wsA, wnA, gn);
        compute(aB, wsB, wnB);
    }

    float bx = __ldg(b + 2 * lane), by = __ldg(b + 2 * lane + 1);
#pragma unroll
    for (int r = 0; r < 8; r++) {
        int row = row0 + r;
        float2 s = unpack2(s2[r]);
        float2 x = unpack2(x2[r]);
        s.x += bx; s.y += by;
        *reinterpret_cast<float2*>(g_S + row * D_H + 2 * lane) = s;
        *reinterpret_cast<float2*>(g_X + row * D_H + 2 * lane) = x;
    }
}

// ================== K2: prefix sum -> rowptr/cursor; zero rowcnt & gsum ====
__global__ void scan_kernel() {
    __shared__ int wsum[32];
    __shared__ int s_total;
    int tid  = threadIdx.x;
    int lane = tid & 31;
    int wid  = tid >> 5;
    int running = 0;

    if (tid < N_GRAPHS * D_H) g_gsum[tid] = 0.f;   // blockDim = 1024 = 16*64

    for (int chunk = 0; chunk < (N_NODES + 1023) / 1024; chunk++) {
        int i = chunk * 1024 + tid;
        int v = 0;
        if (i < N_NODES) {
            v = g_rowcnt[i];
            g_rowcnt[i] = 0;            // self-zero for next launch
        }
        int incl = warp_incl_scan(v);
        if (lane == 31) wsum[wid] = incl;
        __syncthreads();
        if (wid == 0) {
            int wv = wsum[lane];
            int wincl = warp_incl_scan(wv);
            wsum[lane] = wincl;
            if (lane == 31) s_total = wincl;
        }
        __syncthreads();
        int base = (wid > 0) ? wsum[wid - 1] : 0;
        incl += base;
        if (i < N_NODES) {
            g_rowptr[i + 1] = running + incl;
            g_cursor[i]     = running + incl - v;
        }
        if (tid == 0 && chunk == 0) g_rowptr[0] = 0;
        running += s_total;
        __syncthreads();
    }
}

// ================== K3: place (1 edge/thread — single atomic round-trip) ===
__global__ void place_kernel(const int* __restrict__ src,
                             const int* __restrict__ dst) {
    int t = blockIdx.x * blockDim.x + threadIdx.x;
    if (t >= N_EDGES) return;
    int s = src[t];
    int d = dst[t];
    g_csr[atomicAdd(&g_cursor[d], 1)] = s;
}

// ================== K5/K7: layer-2/3 projection (cp.async tile GEMM) =======
// Round-4 proven kernel, instantiated for K=64 only.
template <int K>
__global__ void __launch_bounds__(256, 4)
project_kernel(const float* __restrict__ A,
               const float* __restrict__ Wself,
               const float* __restrict__ Wneigh,
               const float* __restrict__ b) {
    constexpr int KT = K / 32;
    __shared__ float4 sA[2][32][8];
    const int cp   = threadIdx.x;
    const int ty   = threadIdx.y;
    const int tid  = ty * 32 + cp;
    const int base = blockIdx.x * 32;

    const int ldrow = tid >> 3;
    const int ldk4  = tid & 7;
    int grow = base + ldrow;
    if (grow >= N_NODES) grow = N_NODES - 1;
    const float* gsrc = A + grow * K + ldk4 * 4;

    const unsigned long long* Ws = reinterpret_cast<const unsigned long long*>(Wself);
    const unsigned long long* Wn = reinterpret_cast<const unsigned long long*>(Wneigh);

    unsigned long long s2[4], x2[4];
#pragma unroll
    for (int r = 0; r < 4; r++) { s2[r] = 0ull; x2[r] = 0ull; }

    cp_async16((uint32_t)__cvta_generic_to_shared(&sA[0][ldrow][ldk4]), gsrc);
    cp_commit();

#pragma unroll
    for (int kt = 0; kt < KT; kt++) {
        if (kt + 1 < KT) {
            cp_async16((uint32_t)__cvta_generic_to_shared(&sA[(kt + 1) & 1][ldrow][ldk4]),
                       gsrc + (kt + 1) * 32);
            cp_commit();
            cp_wait<1>();
        } else {
            cp_wait<0>();
        }
        __syncthreads();

        const int bufi = kt & 1;
#pragma unroll
        for (int k4 = 0; k4 < 8; k4++) {
            float4 a0 = sA[bufi][ty * 4 + 0][k4];
            float4 a1 = sA[bufi][ty * 4 + 1][k4];
            float4 a2 = sA[bufi][ty * 4 + 2][k4];
            float4 a3 = sA[bufi][ty * 4 + 3][k4];
#pragma unroll
            for (int kk = 0; kk < 4; kk++) {
                int k = kt * 32 + k4 * 4 + kk;
                unsigned long long ws = Ws[k * 32 + cp];
                unsigned long long wn = Wn[k * 32 + cp];
                float v0 = (kk == 0) ? a0.x : (kk == 1) ? a0.y : (kk == 2) ? a0.z : a0.w;
                float v1 = (kk == 0) ? a1.x : (kk == 1) ? a1.y : (kk == 2) ? a1.z : a1.w;
                float v2 = (kk == 0) ? a2.x : (kk == 1) ? a2.y : (kk == 2) ? a2.z : a2.w;
                float v3 = (kk == 0) ? a3.x : (kk == 1) ? a3.y : (kk == 2) ? a3.z : a3.w;
                unsigned long long p0 = pack2(v0, v0);
                unsigned long long p1 = pack2(v1, v1);
                unsigned long long p2 = pack2(v2, v2);
                unsigned long long p3 = pack2(v3, v3);
                ffma2(s2[0], p0, ws); ffma2(x2[0], p0, wn);
                ffma2(s2[1], p1, ws); ffma2(x2[1], p1, wn);
                ffma2(s2[2], p2, ws); ffma2(x2[2], p2, wn);
                ffma2(s2[3], p3, ws); ffma2(x2[3], p3, wn);
            }
        }
        __syncthreads();
    }

    float bx = b[2 * cp], by = b[2 * cp + 1];
#pragma unroll
    for (int r = 0; r < 4; r++) {
        int row = base + ty * 4 + r;
        if (row >= N_NODES) break;
        float2 s = unpack2(s2[r]);
        float2 x = unpack2(x2[r]);
        s.x += bx; s.y += by;
        *reinterpret_cast<float2*>(g_S + row * D_H + 2 * cp) = s;
        *reinterpret_cast<float2*>(g_X + row * D_H + 2 * cp) = x;
    }
}

// ================== gather + finalize (+ optional fused readout) ===========
// 16 lanes/node, 16 nodes/block. With READOUT: block-local smem reduction of
// its 16 output rows, then spread REDG adds into g_gsum.
template <bool RELU, bool READOUT>
__global__ void gather_kernel(float* __restrict__ out,
                              const int* __restrict__ gid) {
    __shared__ float sm_o[16][D_H];

    int t    = blockIdx.x * blockDim.x + threadIdx.x;
    int node = t >> 4;
    int lane = t & 15;

    int beg = g_rowptr[node];
    int end = g_rowptr[node + 1];

    float4 acc = make_float4(0.f, 0.f, 0.f, 0.f);
    int p = beg;
    for (; p + 1 < end; p += 2) {
        int s0 = g_csr[p];
        int s1 = g_csr[p + 1];
        float4 v0 = *reinterpret_cast<const float4*>(g_X + s0 * D_H + lane * 4);
        float4 v1 = *reinterpret_cast<const float4*>(g_X + s1 * D_H + lane * 4);
        acc.x += v0.x; acc.y += v0.y; acc.z += v0.z; acc.w += v0.w;
        acc.x += v1.x; acc.y += v1.y; acc.z += v1.z; acc.w += v1.w;
    }
    if (p < end) {
        int s0 = g_csr[p];
        float4 v0 = *reinterpret_cast<const float4*>(g_X + s0 * D_H + lane * 4);
        acc.x += v0.x; acc.y += v0.y; acc.z += v0.z; acc.w += v0.w;
    }

    float inv = 1.f / fmaxf((float)(end - beg), 1.f);
    float4 s4 = *reinterpret_cast<const float4*>(g_S + node * D_H + lane * 4);
    float4 o;
    o.x = s4.x + acc.x * inv;
    o.y = s4.y + acc.y * inv;
    o.z = s4.z + acc.z * inv;
    o.w = s4.w + acc.w * inv;
    if (RELU) {
        o.x = fmaxf(o.x, 0.f); o.y = fmaxf(o.y, 0.f);
        o.z = fmaxf(o.z, 0.f); o.w = fmaxf(o.w, 0.f);
    }
    *reinterpret_cast<float4*>(out + node * D_H + lane * 4) = o;

    if (READOUT) {
        int nl = threadIdx.x >> 4;                    // node-local 0..15
        *reinterpret_cast<float4*>(&sm_o[nl][lane * 4]) = o;
        __syncthreads();
        if (threadIdx.x < D_H) {
            int c = threadIdx.x;
            int node0 = blockIdx.x * 16;
            int curg = __ldg(gid + node0);
            float s = 0.f;
#pragma unroll
            for (int i = 0; i < 16; i++) {
                int gi = __ldg(gid + node0 + i);
                if (gi != curg) {
                    atomicAdd(&g_gsum[curg * D_H + c], s);
                    curg = gi;
                    s = 0.f;
                }
                s += sm_o[i][c];
            }
            atomicAdd(&g_gsum[curg * D_H + c], s);
        }
    }
}

// ================== K9: head (gsum -> out_feat, out) ======================
__device__ __forceinline__ int lower_bound_gid(const int* gid, int key) {
    int lo = 0, hi = N_NODES;
    while (lo < hi) {
        int mid = (lo + hi) >> 1;
        if (gid[mid] < key) lo = mid + 1; else hi = mid;
    }
    return lo;
}

__global__ void head_kernel(const int* __restrict__ gid,
                            const float* __restrict__ Wcls,
                            const float* __restrict__ bcls,
                            float* __restrict__ out,
                            float* __restrict__ out_feat) {
    __shared__ float sf[D_H];
    __shared__ int s_cnt;
    int g = blockIdx.x;
    if (threadIdx.x == 0)
        s_cnt = lower_bound_gid(gid, g + 1) - lower_bound_gid(gid, g);
    __syncthreads();
    int c = threadIdx.x;            // 0..63
    float m = g_gsum[g * D_H + c] / fmaxf((float)s_cnt, 1.f);
    out_feat[g * D_H + c] = m;
    sf[c] = m;
    __syncthreads();
    if (threadIdx.x < 2) {
        int j = threadIdx.x;
        float s = bcls[j];
#pragma unroll
        for (int k = 0; k < D_H; k++)
            s = fmaf(sf[k], Wcls[k * 2 + j], s);
        out[g * 2 + j] = s;
    }
}

// ---------------- launch ----------------

template <typename T>
static T* sym_addr(const void* sym) {
    void* p = nullptr;
    cudaGetSymbolAddress(&p, sym);
    return (T*)p;
}

extern "C" void kernel_launch(void* const* d_in, const int* in_sizes, int n_in,
                              void* d_out, int out_size) {
    const float* feat     = (const float*)d_in[0];
    const int*   src      = (const int*)d_in[1];
    const int*   dst      = (const int*)d_in[2];
    const int*   gid      = (const int*)d_in[3];
    const float* W_self1  = (const float*)d_in[4];
    const float* W_neigh1 = (const float*)d_in[5];
    const float* b1       = (const float*)d_in[6];
    const float* W_self2  = (const float*)d_in[7];
    const float* W_neigh2 = (const float*)d_in[8];
    const float* b2       = (const float*)d_in[9];
    const float* W_self3  = (const float*)d_in[10];
    const float* W_neigh3 = (const float*)d_in[11];
    const float* b3       = (const float*)d_in[12];
    const float* W_cls    = (const float*)d_in[13];
    const float* b_cls    = (const float*)d_in[14];

    float* out      = (float*)d_out;                  // [16, 2]
    float* out_feat = out + N_GRAPHS * 2;             // [16, 64]
    float* h3       = out_feat + N_GRAPHS * D_H;      // [10000, 64]

    float* p_h1 = sym_addr<float>(g_h1);
    float* p_h2 = sym_addr<float>(g_h2);

    dim3 projBlk(32, 8);
    const int proj64Grid = (N_NODES + 31) / 32;       // 313
    const int gatherGrid = N_NODES * 16 / 256;        // 625
    const int placeGrid  = N_EDGES / 256;             // 1250

    // ---- K1: layer-1 projection fused with dst histogram ----
    fused_proj1_hist<<<PROJ_B + HIST_B, 128>>>(feat, W_self1, W_neigh1, b1, dst);
    // ---- K2: rowptr/cursor scan (also zeroes rowcnt, gsum) ----
    scan_kernel<<<1, 1024>>>();
    // ---- K3: CSR placement ----
    place_kernel<<<placeGrid, 256>>>(src, dst);

    // ---- layer 1 gather ----
    gather_kernel<true, false><<<gatherGrid, 256>>>(p_h1, gid);

    // ---- layer 2 ----
    project_kernel<D_H><<<proj64Grid, projBlk>>>(p_h1, W_self2, W_neigh2, b2);
    gather_kernel<true, false><<<gatherGrid, 256>>>(p_h2, gid);

    // ---- layer 3 (gather fused with per-graph readout sums) ----
    project_kernel<D_H><<<proj64Grid, projBlk>>>(p_h2, W_self3, W_neigh3, b3);
    gather_kernel<false, true><<<gatherGrid, 256>>>(h3, gid);

    // ---- head ----
    head_kernel<<<N_GRAPHS, D_H>>>(gid, W_cls, b_cls, out, out_feat);
}